// round 1
// baseline (speedup 1.0000x reference)
#include <cuda_runtime.h>

// LIF_13984413516471
// B=128 batches, S=128 seq, H=128 hidden, K=8 neurons.
// Sequential scan per batch over T=S*H time steps; each step does K neuron
// sub-steps: s += x; spike = s > th[k]; out = spike ? s : 0; s -= out.
// Output layout: outs[b][i][k][j], spikes[b][i][k][j], t = i*H + j.
//
// Parallelization: speculative chunking. Chunk = one i (128 time steps).
// Phase 1: every chunk simulated from s=0 in parallel (exact for chunk 0 of
// each batch). Phase 2: per-batch sequential fixup; for each chunk, re-simulate
// BOTH the speculative (s=0) and true trajectories until they co-spike
// (after which they are identical), patching outputs along the way.

#define BB 128
#define SS 128
#define HH 128
#define KK 8
#define NCHUNK (BB * SS)

__device__ float g_spec_state[NCHUNK];

__global__ __launch_bounds__(64) void lif_spec_kernel(
    const float* __restrict__ x, const float* __restrict__ th,
    float* __restrict__ outs, float* __restrict__ spikes, int write_spikes)
{
    int chunk = blockIdx.x * blockDim.x + threadIdx.x;
    if (chunk >= NCHUNK) return;

    float t[KK];
#pragma unroll
    for (int k = 0; k < KK; ++k) t[k] = __ldg(th + k);

    const float4* __restrict__ xrow =
        reinterpret_cast<const float4*>(x + (size_t)chunk * HH);
    float* orow = outs + (size_t)chunk * (KK * HH);
    float* srow = spikes + (size_t)chunk * (KK * HH);

    float s = 0.0f;
    float4 xv = xrow[0];

    for (int g = 0; g < HH / 4; ++g) {
        float xarr[4] = {xv.x, xv.y, xv.z, xv.w};
        if (g + 1 < HH / 4) xv = xrow[g + 1];   // prefetch next group

        float ob[4][KK];
#pragma unroll
        for (int jj = 0; jj < 4; ++jj) {
            float xx = xarr[jj];
#pragma unroll
            for (int k = 0; k < KK; ++k) {
                s += xx;
                bool sp = s > t[k];
                ob[jj][k] = sp ? s : 0.0f;
                s = sp ? 0.0f : s;
            }
        }

        int j0 = g * 4;
#pragma unroll
        for (int k = 0; k < KK; ++k) {
            float4 v = make_float4(ob[0][k], ob[1][k], ob[2][k], ob[3][k]);
            *reinterpret_cast<float4*>(orow + k * HH + j0) = v;
            if (write_spikes) {
                float4 sv = make_float4(v.x > 0.0f ? 1.0f : 0.0f,
                                        v.y > 0.0f ? 1.0f : 0.0f,
                                        v.z > 0.0f ? 1.0f : 0.0f,
                                        v.w > 0.0f ? 1.0f : 0.0f);
                *reinterpret_cast<float4*>(srow + k * HH + j0) = sv;
            }
        }
    }
    g_spec_state[chunk] = s;
}

__global__ void lif_fixup_kernel(
    const float* __restrict__ x, const float* __restrict__ th,
    float* __restrict__ outs, float* __restrict__ spikes, int write_spikes)
{
    if (threadIdx.x != 0) return;
    int b = blockIdx.x;

    float t[KK];
#pragma unroll
    for (int k = 0; k < KK; ++k) t[k] = __ldg(th + k);

    float s = 0.0f;   // true carried state
    for (int i = 0; i < SS; ++i) {
        int chunk = b * SS + i;
        if (s == 0.0f) {
            // speculative assumption (s_in = 0) was exact: chunk is correct
            s = g_spec_state[chunk];
            continue;
        }

        const float4* __restrict__ xrow =
            reinterpret_cast<const float4*>(x + (size_t)chunk * HH);
        float* orow = outs + (size_t)chunk * (KK * HH);
        float* srow = spikes + (size_t)chunk * (KK * HH);

        float sa = 0.0f;   // speculative trajectory
        float sb = s;      // true trajectory
        bool merged = false;

        float4 xv = xrow[0];
        for (int g = 0; g < HH / 4 && !merged; ++g) {
            float xarr[4] = {xv.x, xv.y, xv.z, xv.w};
            if (g + 1 < HH / 4) xv = xrow[g + 1];

            for (int jj = 0; jj < 4 && !merged; ++jj) {
                int j = g * 4 + jj;
                float xx = xarr[jj];
#pragma unroll
                for (int k = 0; k < KK; ++k) {
                    if (merged) break;
                    sa += xx;
                    sb += xx;
                    bool spa = sa > t[k];
                    bool spb = sb > t[k];
                    int idx = k * HH + j;
                    if (spa && spb) {
                        // co-spike: trajectories identical from here on.
                        // spike bit already 1 in speculative output; patch value.
                        orow[idx] = sb;
                        merged = true;
                    } else {
                        orow[idx] = spb ? sb : 0.0f;
                        if (write_spikes) srow[idx] = spb ? 1.0f : 0.0f;
                        if (spa) sa = 0.0f;
                        if (spb) sb = 0.0f;
                    }
                }
            }
        }
        s = merged ? g_spec_state[chunk] : sb;
    }
}

extern "C" void kernel_launch(void* const* d_in, const int* in_sizes, int n_in,
                              void* d_out, int out_size) {
    const float* x  = (const float*)d_in[0];   // (B, S, H) f32
    const float* th = (const float*)d_in[1];   // (K,) f32
    float* outs = (float*)d_out;

    const long long N = (long long)BB * SS * KK * HH;   // 16777216
    int write_spikes = ((long long)out_size >= 2 * N) ? 1 : 0;
    float* spikes = outs + N;

    lif_spec_kernel<<<NCHUNK / 64, 64>>>(x, th, outs, spikes, write_spikes);
    lif_fixup_kernel<<<BB, 32>>>(x, th, outs, spikes, write_spikes);
}